// round 2
// baseline (speedup 1.0000x reference)
#include <cuda_runtime.h>
#include <cuda_bf16.h>

#define NROWS    8192
#define NF       1024
#define NTHREADS 256
#define NBLOCKS  1024
#define PAD      9          // odd stride -> conflict-free LDS across lanes

__global__ __launch_bounds__(NTHREADS)
void kan_fused2(const float* __restrict__ x,
                const float* __restrict__ lnw,
                const float* __restrict__ lnb,
                const float* __restrict__ sw,
                const float* __restrict__ bw,
                const float* __restrict__ grid,
                float* __restrict__ out)
{
    __shared__ float s_sw[NF * PAD];        // spline weights pre-scaled by 1/6
    __shared__ float s_red[2][4][8];        // [parity][{sum0,sq0,sum1,sq1}][warp]

    const int tid  = threadIdx.x;
    const int wid  = tid >> 5;
    const int lane = tid & 31;

    // Stage spline weights, pre-scaled by 1/6 (bases then sum to 6)
    for (int f = tid; f < NF; f += NTHREADS) {
        float4 a = *reinterpret_cast<const float4*>(sw + f * 8);
        float4 b = *reinterpret_cast<const float4*>(sw + f * 8 + 4);
        float* d = s_sw + f * PAD;
        d[0] = a.x * (1.0f/6.0f); d[1] = a.y * (1.0f/6.0f);
        d[2] = a.z * (1.0f/6.0f); d[3] = a.w * (1.0f/6.0f);
        d[4] = b.x * (1.0f/6.0f); d[5] = b.y * (1.0f/6.0f);
        d[6] = b.z * (1.0f/6.0f); d[7] = b.w * (1.0f/6.0f);
    }

    const float g0    = grid[0];
    const float g11   = grid[11];
    const float inv_h = 11.0f / (g11 - g0);
    const float h     = (g11 - g0) * (1.0f / 11.0f);

    // Per-thread fixed feature params, with grid scale folded into LN affine
    float A[4], G[4], W[4];
    const float* wfp[4];
    #pragma unroll
    for (int e = 0; e < 4; e++) {
        int f = tid + e * NTHREADS;
        A[e] = lnw[f] * inv_h;            // slope in knot units
        G[e] = (lnb[f] - g0) * inv_h;     // offset in knot units
        W[e] = bw[f];
        wfp[e] = s_sw + f * PAD;
    }
    __syncthreads();

    int par = 0;
    // 2 rows per iteration; all blocks do exactly NROWS/2/NBLOCKS iterations
    for (int p = blockIdx.x; p < NROWS / 2; p += NBLOCKS, par ^= 1) {
        const float* xr = x + (size_t)(2 * p) * NF;

        float v0[4], v1[4];
        float s0 = 0.f, q0 = 0.f, s1 = 0.f, q1 = 0.f;
        #pragma unroll
        for (int e = 0; e < 4; e++) {
            float a = xr[tid + e * NTHREADS];
            float b = xr[NF + tid + e * NTHREADS];
            v0[e] = a; v1[e] = b;
            s0 += a; q0 = fmaf(a, a, q0);
            s1 += b; q1 = fmaf(b, b, q1);
        }

        #pragma unroll
        for (int off = 16; off; off >>= 1) {
            s0 += __shfl_xor_sync(0xffffffffu, s0, off);
            q0 += __shfl_xor_sync(0xffffffffu, q0, off);
            s1 += __shfl_xor_sync(0xffffffffu, s1, off);
            q1 += __shfl_xor_sync(0xffffffffu, q1, off);
        }
        if (lane == 0) {
            s_red[par][0][wid] = s0;
            s_red[par][1][wid] = q0;
            s_red[par][2][wid] = s1;
            s_red[par][3][wid] = q1;
        }
        __syncthreads();   // only barrier per 2 rows (double-buffered scratch)

        float t0 = 0.f, u0 = 0.f, t1 = 0.f, u1 = 0.f;
        #pragma unroll
        for (int i = 0; i < 8; i++) {
            t0 += s_red[par][0][i];
            u0 += s_red[par][1][i];
            t1 += s_red[par][2][i];
            u1 += s_red[par][3][i];
        }

        const float mu0 = t0 * (1.0f / NF);
        const float r0  = rsqrtf(u0 * (1.0f / NF) - mu0 * mu0 + 1e-5f);
        const float mu1 = t1 * (1.0f / NF);
        const float r1  = rsqrtf(u1 * (1.0f / NF) - mu1 * mu1 + 1e-5f);

        float* o0 = out + (size_t)(2 * p) * NF;
        float* o1 = o0 + NF;

        #pragma unroll
        for (int e = 0; e < 4; e++) {
            const int idx = tid + e * NTHREADS;
            const float* wf = wfp[e];

            #pragma unroll
            for (int r = 0; r < 2; r++) {
                const float v    = r ? v1[e] : v0[e];
                const float mu   = r ? mu1 : mu0;
                const float rstd = r ? r1 : r0;

                const float c  = (v - mu) * rstd;
                const float xn = fmaf(c, A[e], G[e]);     // knot units
                const float n  = fmaf(xn, h, g0);         // normed value

                const float fj = floorf(xn);
                const int   j  = (int)fj;
                const float t  = xn - fj;
                const float u  = 1.0f - t;
                const float t2 = t * t;
                const float B0 = u * u * u;
                const float B1 = fmaf(fmaf(3.0f, t, -6.0f), t2, 4.0f);
                const float B3 = t2 * t;
                const float B2 = 6.0f - B0 - B1 - B3;

                const int i0 = j - 3;
                float s = 0.0f;
                if ((unsigned)(i0    ) < 8u) s = fmaf(B0, wf[i0    ], s);
                if ((unsigned)(i0 + 1) < 8u) s = fmaf(B1, wf[i0 + 1], s);
                if ((unsigned)(i0 + 2) < 8u) s = fmaf(B2, wf[i0 + 2], s);
                if ((unsigned)(i0 + 3) < 8u) s = fmaf(B3, wf[i0 + 3], s);

                const float sil = __fdividef(n, 1.0f + __expf(-n));
                const float res = fmaf(W[e], sil, s);

                if (r) o1[idx] = res; else o0[idx] = res;
            }
        }
    }
}

extern "C" void kernel_launch(void* const* d_in, const int* in_sizes, int n_in,
                              void* d_out, int out_size)
{
    const float* x    = (const float*)d_in[0];
    const float* lnw  = (const float*)d_in[1];
    const float* lnb  = (const float*)d_in[2];
    const float* sw   = (const float*)d_in[3];
    const float* bw   = (const float*)d_in[4];
    const float* grid = (const float*)d_in[5];
    float* out = (float*)d_out;

    kan_fused2<<<NBLOCKS, NTHREADS>>>(x, lnw, lnb, sw, bw, grid, out);
}

// round 3
// speedup vs baseline: 1.8257x; 1.8257x over previous
#include <cuda_runtime.h>
#include <cuda_bf16.h>

#define NROWS    8192
#define NF       1024
#define NTHREADS 256
#define NBLOCKS  1024

__global__ __launch_bounds__(NTHREADS)
void kan_fused3(const float* __restrict__ x,
                const float* __restrict__ lnw,
                const float* __restrict__ lnb,
                const float* __restrict__ sw,
                const float* __restrict__ bw,
                const float* __restrict__ grid,
                float* __restrict__ out)
{
    // Transposed coefficient planes: s_swT[i*NF + f]. Tap address stride per
    // coeff index is 1024 words == 0 mod 32 banks, so bank = f mod 32 = lane:
    // conflict-free LDS even with data-dependent (divergent) knot indices.
    __shared__ float s_swT[8 * NF];
    __shared__ float s_red[2][2][8];   // [parity][{sum,sumsq}][warp]

    const int tid  = threadIdx.x;
    const int wid  = tid >> 5;
    const int lane = tid & 31;

    // Stage spline weights pre-scaled by 1/6 into transposed layout
    for (int f = tid; f < NF; f += NTHREADS) {
        float4 a = *reinterpret_cast<const float4*>(sw + f * 8);
        float4 b = *reinterpret_cast<const float4*>(sw + f * 8 + 4);
        s_swT[0 * NF + f] = a.x * (1.0f/6.0f);
        s_swT[1 * NF + f] = a.y * (1.0f/6.0f);
        s_swT[2 * NF + f] = a.z * (1.0f/6.0f);
        s_swT[3 * NF + f] = a.w * (1.0f/6.0f);
        s_swT[4 * NF + f] = b.x * (1.0f/6.0f);
        s_swT[5 * NF + f] = b.y * (1.0f/6.0f);
        s_swT[6 * NF + f] = b.z * (1.0f/6.0f);
        s_swT[7 * NF + f] = b.w * (1.0f/6.0f);
    }

    const float g0    = grid[0];
    const float g11   = grid[11];
    const float inv_h = 11.0f / (g11 - g0);
    const float h     = (g11 - g0) * (1.0f / 11.0f);

    // Per-thread per-feature params with grid scale folded into LN affine
    float A[4], G[4], W[4];
    #pragma unroll
    for (int e = 0; e < 4; e++) {
        int f = tid + e * NTHREADS;
        A[e] = lnw[f] * inv_h;
        G[e] = (lnb[f] - g0) * inv_h;
        W[e] = bw[f];
    }
    __syncthreads();

    int par = 0;
    for (int row = blockIdx.x; row < NROWS; row += NBLOCKS, par ^= 1) {
        const float* xr = x + (size_t)row * NF;

        float v[4];
        float sum = 0.0f, sq = 0.0f;
        #pragma unroll
        for (int e = 0; e < 4; e++) {
            v[e] = xr[tid + e * NTHREADS];
            sum += v[e];
            sq   = fmaf(v[e], v[e], sq);
        }

        #pragma unroll
        for (int off = 16; off; off >>= 1) {
            sum += __shfl_xor_sync(0xffffffffu, sum, off);
            sq  += __shfl_xor_sync(0xffffffffu, sq,  off);
        }
        if (lane == 0) { s_red[par][0][wid] = sum; s_red[par][1][wid] = sq; }
        __syncthreads();   // single barrier/row (parity double-buffer)

        float tot = 0.0f, tot2 = 0.0f;
        #pragma unroll
        for (int i = 0; i < 8; i++) {
            tot  += s_red[par][0][i];
            tot2 += s_red[par][1][i];
        }

        const float mu   = tot * (1.0f / NF);
        const float rstd = rsqrtf(tot2 * (1.0f / NF) - mu * mu + 1e-5f);

        float* outr = out + (size_t)row * NF;

        #pragma unroll
        for (int e = 0; e < 4; e++) {
            const int f = tid + e * NTHREADS;

            const float c  = (v[e] - mu) * rstd;
            const float xn = fmaf(c, A[e], G[e]);   // in knot units
            const float n  = fmaf(xn, h, g0);       // normed value (for silu)

            const float fj = floorf(xn);
            const int   j  = (int)fj;
            const float t  = xn - fj;
            const float u  = 1.0f - t;
            const float t2 = t * t;
            const float B0 = u * u * u;
            const float B1 = fmaf(fmaf(3.0f, t, -6.0f), t2, 4.0f);
            const float B3 = t2 * t;
            const float B2 = 6.0f - B0 - B1 - B3;

            const int i0 = j - 3;
            const float* wf = s_swT + f;   // plane-indexed taps, bank = lane
            float s = 0.0f;
            if ((unsigned)(i0    ) < 8u) s = fmaf(B0, wf[(i0    ) << 10], s);
            if ((unsigned)(i0 + 1) < 8u) s = fmaf(B1, wf[(i0 + 1) << 10], s);
            if ((unsigned)(i0 + 2) < 8u) s = fmaf(B2, wf[(i0 + 2) << 10], s);
            if ((unsigned)(i0 + 3) < 8u) s = fmaf(B3, wf[(i0 + 3) << 10], s);

            const float sil = __fdividef(n, 1.0f + __expf(-n));
            outr[f] = fmaf(W[e], sil, s);
        }
    }
}

extern "C" void kernel_launch(void* const* d_in, const int* in_sizes, int n_in,
                              void* d_out, int out_size)
{
    const float* x    = (const float*)d_in[0];
    const float* lnw  = (const float*)d_in[1];
    const float* lnb  = (const float*)d_in[2];
    const float* sw   = (const float*)d_in[3];
    const float* bw   = (const float*)d_in[4];
    const float* grid = (const float*)d_in[5];
    float* out = (float*)d_out;

    kan_fused3<<<NBLOCKS, NTHREADS>>>(x, lnw, lnb, sw, bw, grid, out);
}